// round 10
// baseline (speedup 1.0000x reference)
#include <cuda_runtime.h>
#include <math.h>
#include <stdint.h>

// hidden_states: [16, 13, 512, 768] fp32, reduce over axis=2 (512)
// out: [16, 13, 2304] = concat(sum, std(ddof=1), max).
//
// R10: R9 (2-CTA cluster + DSMEM merge) with
//   - 5-stage pipeline (60KB bufs): ~14 outstanding bulk ops/SM
//   - float4 consumer, TPB=192: thread t owns h4-column t (h = 4t..4t+3),
//     768 LDS.128 per 12KB stage, conflict-free; vector DSMEM + output.

#define BL     208
#define SEQ    512
#define HID    768
#define H4     192             // float4 per row
#define RPC    256             // rows per CTA
#define SROWS  4               // rows per stage
#define NST    5               // pipeline stages
#define NITER  (RPC / SROWS)   // 64
#define TPB    192
#define STAGE_BYTES (SROWS * HID * 4)   // 12288

__device__ __forceinline__ uint32_t smem_u32(const void* p) {
    uint32_t a;
    asm("{ .reg .u64 t; cvta.to.shared.u64 t, %1; cvt.u32.u64 %0, t; }"
        : "=r"(a) : "l"(p));
    return a;
}
__device__ __forceinline__ void mbar_init(uint32_t bar, uint32_t cnt) {
    asm volatile("mbarrier.init.shared.b64 [%0], %1;" :: "r"(bar), "r"(cnt) : "memory");
}
__device__ __forceinline__ void mbar_arrive(uint32_t bar) {
    asm volatile("mbarrier.arrive.shared.b64 _, [%0];" :: "r"(bar) : "memory");
}
__device__ __forceinline__ void mbar_expect_tx(uint32_t bar, uint32_t tx) {
    asm volatile("mbarrier.arrive.expect_tx.shared.b64 _, [%0], %1;"
                 :: "r"(bar), "r"(tx) : "memory");
}
__device__ __forceinline__ void mbar_wait(uint32_t bar, uint32_t parity) {
    asm volatile(
        "{\n\t"
        ".reg .pred P;\n\t"
        "LAB_WAIT_%=:\n\t"
        "mbarrier.try_wait.parity.acquire.cta.shared::cta.b64 P, [%0], %1, 0x989680;\n\t"
        "@P bra.uni LAB_DONE_%=;\n\t"
        "bra.uni LAB_WAIT_%=;\n\t"
        "LAB_DONE_%=:\n\t"
        "}"
        :: "r"(bar), "r"(parity) : "memory");
}
__device__ __forceinline__ void bulk_ld(uint32_t dst_smem, const void* src,
                                        uint32_t bytes, uint32_t bar) {
    asm volatile(
        "cp.async.bulk.shared::cta.global.mbarrier::complete_tx::bytes "
        "[%0], [%1], %2, [%3];"
        :: "r"(dst_smem), "l"(src), "r"(bytes), "r"(bar) : "memory");
}
__device__ __forceinline__ uint32_t mapa_rank(uint32_t addr, uint32_t rank) {
    uint32_t r;
    asm("mapa.shared::cluster.u32 %0, %1, %2;" : "=r"(r) : "r"(addr), "r"(rank));
    return r;
}
__device__ __forceinline__ void st_cluster_v4(uint32_t addr, float4 v) {
    asm volatile("st.shared::cluster.v4.f32 [%0], {%1, %2, %3, %4};"
                 :: "r"(addr), "f"(v.x), "f"(v.y), "f"(v.z), "f"(v.w) : "memory");
}

__global__ void __launch_bounds__(TPB) __cluster_dims__(2, 1, 1)
meanstdmax_kernel(const float* __restrict__ in, float* __restrict__ out)
{
    __shared__ __align__(128) float4 buf[NST][SROWS * H4];   // 60 KB
    __shared__ __align__(16)  float4 part[3 * H4];           // 9 KB (rank0 recv)
    __shared__ __align__(8)   uint64_t full_bar[NST];
    __shared__ __align__(8)   uint64_t empty_bar[NST];

    const int tid = threadIdx.x;

    uint32_t rank;
    asm("mov.u32 %0, %%cluster_ctarank;" : "=r"(rank));

    const int bl = blockIdx.x >> 1;     // cluster id
    const float* base = in + (size_t)bl * SEQ * HID + (size_t)rank * RPC * HID;

    uint32_t full_a  = smem_u32(&full_bar[0]);
    uint32_t empty_a = smem_u32(&empty_bar[0]);
    uint32_t part_a  = smem_u32(&part[0]);
    uint32_t buf_a[NST];
    #pragma unroll
    for (int s = 0; s < NST; s++) buf_a[s] = smem_u32(&buf[s][0]);

    if (tid == 0) {
        #pragma unroll
        for (int s = 0; s < NST; s++) {
            mbar_init(full_a  + s * 8, 1);
            mbar_init(empty_a + s * 8, TPB);
        }
    }
    __syncthreads();

    if (tid == 0) {
        #pragma unroll
        for (int s = 0; s < NST; s++) {
            mbar_expect_tx(full_a + s * 8, STAGE_BYTES);
            bulk_ld(buf_a[s], base + (size_t)s * SROWS * HID, STAGE_BYTES,
                    full_a + s * 8);
        }
    }

    // thread t owns float4 column t: h = 4t .. 4t+3
    float4 s4  = make_float4(0.f, 0.f, 0.f, 0.f);
    float4 q4  = make_float4(0.f, 0.f, 0.f, 0.f);
    float4 mx4 = make_float4(-INFINITY, -INFINITY, -INFINITY, -INFINITY);

    for (int it = 0; it < NITER; it++) {
        const int st = it % NST;
        const uint32_t par = (uint32_t)(it / NST) & 1u;

        mbar_wait(full_a + st * 8, par);

        const float4* b = &buf[st][0];
        #pragma unroll
        for (int r = 0; r < SROWS; r++) {
            float4 v = b[r * H4 + tid];
            s4.x += v.x;  s4.y += v.y;  s4.z += v.z;  s4.w += v.w;
            q4.x += v.x * v.x;  q4.y += v.y * v.y;
            q4.z += v.z * v.z;  q4.w += v.w * v.w;
            mx4.x = fmaxf(mx4.x, v.x);  mx4.y = fmaxf(mx4.y, v.y);
            mx4.z = fmaxf(mx4.z, v.z);  mx4.w = fmaxf(mx4.w, v.w);
        }

        mbar_arrive(empty_a + st * 8);

        if (tid == 0 && it + NST < NITER) {
            mbar_wait(empty_a + st * 8, par);
            mbar_expect_tx(full_a + st * 8, STAGE_BYTES);
            bulk_ld(buf_a[st], base + (size_t)(it + NST) * SROWS * HID,
                    STAGE_BYTES, full_a + st * 8);
        }
    }

    // rank1 -> rank0 DSMEM: part[stat*H4 + t]
    if (rank == 1) {
        uint32_t r0 = mapa_rank(part_a, 0);
        st_cluster_v4(r0 + 16u * (uint32_t)tid,            s4);
        st_cluster_v4(r0 + 16u * (uint32_t)(H4 + tid),     q4);
        st_cluster_v4(r0 + 16u * (uint32_t)(2 * H4 + tid), mx4);
    }

    asm volatile("barrier.cluster.arrive.aligned;" ::: "memory");
    asm volatile("barrier.cluster.wait.aligned;"   ::: "memory");

    if (rank == 0) {
        float4 a = part[tid];
        float4 b = part[H4 + tid];
        float4 c = part[2 * H4 + tid];
        s4.x += a.x;  s4.y += a.y;  s4.z += a.z;  s4.w += a.w;
        q4.x += b.x;  q4.y += b.y;  q4.z += b.z;  q4.w += b.w;
        mx4.x = fmaxf(mx4.x, c.x);  mx4.y = fmaxf(mx4.y, c.y);
        mx4.z = fmaxf(mx4.z, c.z);  mx4.w = fmaxf(mx4.w, c.w);

        const float inv_n  = 1.0f / SEQ;
        const float inv_n1 = 1.0f / (SEQ - 1);
        float4 sd;
        sd.x = sqrtf(fmaxf((q4.x - s4.x * (s4.x * inv_n)) * inv_n1, 0.0f));
        sd.y = sqrtf(fmaxf((q4.y - s4.y * (s4.y * inv_n)) * inv_n1, 0.0f));
        sd.z = sqrtf(fmaxf((q4.z - s4.z * (s4.z * inv_n)) * inv_n1, 0.0f));
        sd.w = sqrtf(fmaxf((q4.w - s4.w * (s4.w * inv_n)) * inv_n1, 0.0f));

        float4* o = reinterpret_cast<float4*>(out + (size_t)bl * (3 * HID));
        o[tid]            = s4;
        o[H4 + tid]       = sd;
        o[2 * H4 + tid]   = mx4;
    }
}

extern "C" void kernel_launch(void* const* d_in, const int* in_sizes, int n_in,
                              void* d_out, int out_size)
{
    const float* in = (const float*)d_in[0];
    float* out = (float*)d_out;

    meanstdmax_kernel<<<BL * 2, TPB>>>(in, out);   // 416 CTAs, 208 clusters of 2
}